// round 12
// baseline (speedup 1.0000x reference)
#include <cuda_runtime.h>
#include <math.h>
#include <stdint.h>

#define S_LEN 2048
#define HDIM  1024
#define NHEADS 16
#define NKVH   8
#define DHEAD  64
#define NLAYER 2
#define NEXP   8
#define TOPK   2
#define IDIM   1024
#define EMB_MULT_F 12.0f
#define RES_MULT_F 0.22f
#define ATTN_MULT_F 0.015625f

// ---------------- scratch (static device globals; no runtime allocation) ----
__device__ float g_h [S_LEN*HDIM];
__device__ float g_x [S_LEN*HDIM];
__device__ float g_q [S_LEN*NHEADS*DHEAD];
__device__ float g_k [S_LEN*NKVH*DHEAD];
__device__ float g_v [S_LEN*NKVH*DHEAD];
__device__ float g_ao[S_LEN*NHEADS*DHEAD];
__device__ float g_u [(size_t)NEXP*S_LEN*IDIM];
__device__ float g_t [(size_t)NEXP*S_LEN*IDIM];
__device__ float g_y [(size_t)NEXP*S_LEN*HDIM];
__device__ int   g_cnt [NEXP];
__device__ int   g_list[NEXP*S_LEN];
__device__ int   g_slot[S_LEN*TOPK];
__device__ float g_wt  [S_LEN*TOPK];

// ---------------- tf32 tensor-core GEMM: 128x128 tile, BK=16, 8 warps -------
// 2-stage shared-memory double buffer: one __syncthreads per K-tile.
#define BM 128
#define BN 128
#define BKT 16
#define AS_STRIDE 20    // conflict-free for A-fragment LDS pattern
#define BS_STRIDE 136   // conflict-free for B-fragment LDS pattern

__device__ __forceinline__ uint32_t f2tf(float f) {
    uint32_t u; asm("cvt.rna.tf32.f32 %0, %1;" : "=r"(u) : "f"(f)); return u;
}

__device__ __forceinline__ void mma8(float* d, const uint32_t* a, const uint32_t* b) {
    asm volatile(
        "mma.sync.aligned.m16n8k8.row.col.f32.tf32.tf32.f32 "
        "{%0,%1,%2,%3},{%4,%5,%6,%7},{%8,%9},{%0,%1,%2,%3};"
        : "+f"(d[0]), "+f"(d[1]), "+f"(d[2]), "+f"(d[3])
        : "r"(a[0]), "r"(a[1]), "r"(a[2]), "r"(a[3]), "r"(b[0]), "r"(b[1]));
}

__device__ __forceinline__ void mma_core(
    const float* __restrict__ A, const float* __restrict__ B, float* __restrict__ C,
    int Meff, int N, int K, int col0, const int* __restrict__ gather,
    float alpha, bool accum)
{
    __shared__ __align__(16) uint32_t As[2][BM*AS_STRIDE];
    __shared__ __align__(16) uint32_t Bs[2][BKT*BS_STRIDE];

    int row0 = blockIdx.y * BM;
    if (row0 >= Meff) return;
    int tid  = threadIdx.x;
    int lane = tid & 31, wid = tid >> 5;
    int wm = wid & 3, wn = wid >> 2;      // warp tile: rows wm*32, cols wn*64

    // A loader: thread -> (row = tid>>1, cols (tid&1)*8 .. +7)
    int arow = tid >> 1;
    int acol = (tid & 1) * 8;
    int grow = row0 + arow;
    bool aok = (grow < Meff);
    const float* Arow = A;
    if (aok) { int src = gather ? gather[grow] : grow; Arow = A + (size_t)src * K; }
    // B loader: thread -> (row = tid>>4, cols (tid&15)*8 .. +7)
    int brow = tid >> 4;
    int bcol = (tid & 15) * 8;
    const float* Bp = B + (size_t)brow * N + col0 + bcol;

    float acc[2][8][4];
#pragma unroll
    for (int mt = 0; mt < 2; mt++)
#pragma unroll
        for (int nt = 0; nt < 8; nt++)
#pragma unroll
            for (int i = 0; i < 4; i++) acc[mt][nt][i] = 0.f;

    float ra[8], rb[8];

    auto LOADT = [&](int k0) {
        if (aok) {
            float4 t0 = *(const float4*)(Arow + k0 + acol);
            float4 t1 = *(const float4*)(Arow + k0 + acol + 4);
            ra[0]=t0.x; ra[1]=t0.y; ra[2]=t0.z; ra[3]=t0.w;
            ra[4]=t1.x; ra[5]=t1.y; ra[6]=t1.z; ra[7]=t1.w;
        } else {
#pragma unroll
            for (int i = 0; i < 8; i++) ra[i] = 0.f;
        }
        float4 u0 = *(const float4*)(Bp + (size_t)k0 * N);
        float4 u1 = *(const float4*)(Bp + (size_t)k0 * N + 4);
        rb[0]=u0.x; rb[1]=u0.y; rb[2]=u0.z; rb[3]=u0.w;
        rb[4]=u1.x; rb[5]=u1.y; rb[6]=u1.z; rb[7]=u1.w;
    };
    auto STORET = [&](int st) {
        uint4 pa0 = make_uint4(f2tf(ra[0]), f2tf(ra[1]), f2tf(ra[2]), f2tf(ra[3]));
        uint4 pa1 = make_uint4(f2tf(ra[4]), f2tf(ra[5]), f2tf(ra[6]), f2tf(ra[7]));
        *(uint4*)&As[st][arow*AS_STRIDE + acol]     = pa0;
        *(uint4*)&As[st][arow*AS_STRIDE + acol + 4] = pa1;
        uint4 pb0 = make_uint4(f2tf(rb[0]), f2tf(rb[1]), f2tf(rb[2]), f2tf(rb[3]));
        uint4 pb1 = make_uint4(f2tf(rb[4]), f2tf(rb[5]), f2tf(rb[6]), f2tf(rb[7]));
        *(uint4*)&Bs[st][brow*BS_STRIDE + bcol]     = pb0;
        *(uint4*)&Bs[st][brow*BS_STRIDE + bcol + 4] = pb1;
    };
    auto COMPUTE = [&](int st) {
#pragma unroll
        for (int ks = 0; ks < 2; ks++) {
            const int kk = ks * 8;
            uint32_t af[2][4];
            int r    = wm*32 + (lane >> 2);
            int ccol = kk + (lane & 3);
#pragma unroll
            for (int mt = 0; mt < 2; mt++) {
                int rr = r + mt*16;
                af[mt][0] = As[st][(rr    )*AS_STRIDE + ccol];
                af[mt][1] = As[st][(rr + 8)*AS_STRIDE + ccol];
                af[mt][2] = As[st][(rr    )*AS_STRIDE + ccol + 4];
                af[mt][3] = As[st][(rr + 8)*AS_STRIDE + ccol + 4];
            }
#pragma unroll
            for (int nt = 0; nt < 8; nt++) {
                int cn = wn*64 + nt*8 + (lane >> 2);
                uint32_t bf[2];
                bf[0] = Bs[st][(kk + (lane & 3)    )*BS_STRIDE + cn];
                bf[1] = Bs[st][(kk + (lane & 3) + 4)*BS_STRIDE + cn];
                mma8(acc[0][nt], af[0], bf);
                mma8(acc[1][nt], af[1], bf);
            }
        }
    };

    LOADT(0);
    STORET(0);
    __syncthreads();
    int stage = 0;
    for (int k0 = BKT; k0 < K; k0 += BKT) {
        LOADT(k0);              // prefetch next tile into registers
        COMPUTE(stage);         // compute current smem stage
        STORET(stage ^ 1);      // write next stage (no conflict with compute)
        __syncthreads();
        stage ^= 1;
    }
    COMPUTE(stage);

    // epilogue
#pragma unroll
    for (int mt = 0; mt < 2; mt++) {
        int rbase = row0 + wm*32 + mt*16 + (lane >> 2);
#pragma unroll
        for (int half = 0; half < 2; half++) {
            int r = rbase + half*8;
            if (r >= Meff) continue;
            float* Crow = C + (size_t)r * N;
#pragma unroll
            for (int nt = 0; nt < 8; nt++) {
                int c = col0 + wn*64 + nt*8 + (lane & 3)*2;
                float x = alpha * acc[mt][nt][half*2 + 0];
                float y = alpha * acc[mt][nt][half*2 + 1];
                if (accum) {
                    Crow[c]   += x;
                    Crow[c+1] += y;
                } else {
                    float2 vv = make_float2(x, y);
                    *(float2*)(Crow + c) = vv;
                }
            }
        }
    }
}

__global__ __launch_bounds__(256) void k_sgemm(
    const float* A, const float* B, float* C,
    int M, int N, int K, float alpha, int accum)
{
    mma_core(A, B, C, M, N, K, blockIdx.x*BN, nullptr, alpha, accum != 0);
}

// fused QKV: one launch, blockIdx.x 0..15 spans q(0-7), k(8-11), v(12-15)
__global__ __launch_bounds__(256) void k_sgemm_qkv(
    const float* __restrict__ A,
    const float* __restrict__ Wq, const float* __restrict__ Wk, const float* __restrict__ Wv,
    float* __restrict__ q, float* __restrict__ k, float* __restrict__ v)
{
    int nb = blockIdx.x;
    const float* B; float* C; int N; int cb;
    if (nb < 8)       { B = Wq; C = q; N = 1024; cb = nb; }
    else if (nb < 12) { B = Wk; C = k; N = 512;  cb = nb - 8; }
    else              { B = Wv; C = v; N = 512;  cb = nb - 12; }
    mma_core(A, B, C, S_LEN, N, HDIM, cb*BN, nullptr, 1.f, false);
}

// one launch covers all 8 experts via blockIdx.z; blocks past cnt[e] exit early
__global__ __launch_bounds__(256) void k_sgemm_moe(
    const float* A, long aStride,
    const float* B, long bStride,
    float* C, long cStride,
    const int* gatherBase, const int* cnt, int N, int K)
{
    int e = blockIdx.z;
    mma_core(A + (size_t)e*aStride, B + (size_t)e*bStride, C + (size_t)e*cStride,
             cnt[e], N, K, blockIdx.x*BN,
             gatherBase ? gatherBase + e*S_LEN : nullptr, 1.f, false);
}

// ---------------- embedding ------------------------------------------------
__global__ __launch_bounds__(256) void k_embed(
    const int* __restrict__ ids, const float* __restrict__ emb, float* __restrict__ h)
{
    int t = blockIdx.x;
    int id = ids[t];
    const float* er = emb + (size_t)id * HDIM;
    for (int c = threadIdx.x; c < HDIM; c += 256)
        h[(size_t)t*HDIM + c] = er[c] * EMB_MULT_F;
}

// ---------------- rmsnorm ---------------------------------------------------
__global__ __launch_bounds__(256) void k_rmsnorm(
    const float* __restrict__ in, const float* __restrict__ w, float* __restrict__ out)
{
    int t = blockIdx.x;
    const float* xr = in + (size_t)t * HDIM;
    float s = 0.f;
    for (int c = threadIdx.x; c < HDIM; c += 256) { float vv = xr[c]; s += vv*vv; }
    __shared__ float red[256];
    red[threadIdx.x] = s;
    __syncthreads();
    for (int o = 128; o > 0; o >>= 1) {
        if (threadIdx.x < o) red[threadIdx.x] += red[threadIdx.x + o];
        __syncthreads();
    }
    float scale = rsqrtf(red[0] * (1.f/HDIM) + 1e-6f);
    for (int c = threadIdx.x; c < HDIM; c += 256)
        out[(size_t)t*HDIM + c] = xr[c] * scale * w[c];
}

// ---------------- RoPE (neox halves), fp32, sincos cached in smem -----------
// exponent: inv_freq(j) = 10000^(-2j/64) = exp2f(-j * log2(10000)/32)
__global__ __launch_bounds__(256) void k_rope(
    float* __restrict__ q, float* __restrict__ kk, const int* __restrict__ pos)
{
    int t = blockIdx.x;
    __shared__ float sc[32], ss[32];
    if (threadIdx.x < 32) {
        float p = (float)pos[t];
        float invf = exp2f((float)threadIdx.x * -0.4152410118f);
        float ang = p * invf;
        ss[threadIdx.x] = sinf(ang);
        sc[threadIdx.x] = cosf(ang);
    }
    __syncthreads();
    // 768 items: (head 0..23) x (pair j 0..31); heads 0-15 -> q, 16-23 -> k
#pragma unroll
    for (int it = threadIdx.x; it < 768; it += 256) {
        int hh = it >> 5, j = it & 31;
        float* base = (hh < 16)
            ? q  + (size_t)t*(NHEADS*DHEAD) + hh*DHEAD
            : kk + (size_t)t*(NKVH*DHEAD)   + (hh - 16)*DHEAD;
        float x1 = base[j], x2 = base[j + 32];
        base[j]      = x1*sc[j] - x2*ss[j];
        base[j + 32] = x2*sc[j] + x1*ss[j];
    }
}

// ---------------- flash attention (fp32, causal, GQA rep=2) -----------------
// float4-vectorized: 4 parallel dot partials break the serial FMA chain.
__global__ __launch_bounds__(64) void k_flash(
    const float* __restrict__ q, const float* __restrict__ k,
    const float* __restrict__ v, float* __restrict__ out)
{
    int head = blockIdx.x;        // 0..15
    int qt   = blockIdx.y;        // 0..31
    int tid  = threadIdx.x;       // 64: one q row per thread
    int m = qt*64 + tid;
    int kvh = head >> 1;

    __shared__ __align__(16) float4 Ks[64][16];
    __shared__ __align__(16) float4 Vs[64][16];

    float4 qv[16], av[16];
    const float4* qp = (const float4*)(q + (size_t)m*(NHEADS*DHEAD) + head*DHEAD);
#pragma unroll
    for (int i = 0; i < 16; i++) {
        float4 tq = qp[i];
        tq.x *= ATTN_MULT_F; tq.y *= ATTN_MULT_F; tq.z *= ATTN_MULT_F; tq.w *= ATTN_MULT_F;
        qv[i] = tq;
        av[i] = make_float4(0.f, 0.f, 0.f, 0.f);
    }

    float mi = -1e30f, li = 0.f;

    for (int jt = 0; jt <= qt; jt++) {
        const float4* kp = (const float4*)(k + (size_t)(jt*64)*(NKVH*DHEAD) + kvh*DHEAD);
        const float4* vp = (const float4*)(v + (size_t)(jt*64)*(NKVH*DHEAD) + kvh*DHEAD);
#pragma unroll
        for (int i = 0; i < 16; i++) {
            int idx = i*64 + tid;
            int r = idx >> 4, c = idx & 15;
            size_t off = (size_t)r * (NKVH*DHEAD/4) + c;
            Ks[r][c] = kp[off];
            Vs[r][c] = vp[off];
        }
        __syncthreads();
        int jmax = (jt == qt) ? (tid + 1) : 64;   // causal within diagonal tile
        for (int j = 0; j < jmax; j++) {
            float4 s4 = make_float4(0.f, 0.f, 0.f, 0.f);
#pragma unroll
            for (int i = 0; i < 16; i++) {
                float4 kk4 = Ks[j][i];
                s4.x += qv[i].x * kk4.x;
                s4.y += qv[i].y * kk4.y;
                s4.z += qv[i].z * kk4.z;
                s4.w += qv[i].w * kk4.w;
            }
            float s = (s4.x + s4.y) + (s4.z + s4.w);
            if (s > mi) {
                float corr = __expf(mi - s);
                li = li*corr + 1.f;
#pragma unroll
                for (int i = 0; i < 16; i++) {
                    float4 vv = Vs[j][i];
                    av[i].x = av[i].x*corr + vv.x;
                    av[i].y = av[i].y*corr + vv.y;
                    av[i].z = av[i].z*corr + vv.z;
                    av[i].w = av[i].w*corr + vv.w;
                }
                mi = s;
            } else {
                float pp = __expf(s - mi);
                li += pp;
#pragma unroll
                for (int i = 0; i < 16; i++) {
                    float4 vv = Vs[j][i];
                    av[i].x += pp*vv.x;
                    av[i].y += pp*vv.y;
                    av[i].z += pp*vv.z;
                    av[i].w += pp*vv.w;
                }
            }
        }
        __syncthreads();
    }
    float inv = 1.f / li;
    float4* op = (float4*)(out + (size_t)m*(NHEADS*DHEAD) + head*DHEAD);
#pragma unroll
    for (int i = 0; i < 16; i++) {
        float4 r = av[i];
        r.x *= inv; r.y *= inv; r.z *= inv; r.w *= inv;
        op[i] = r;
    }
}

// ---------------- gating: logits, top-2, softmax, expert lists --------------
__global__ void k_zero_cnt(int* cnt) { if (threadIdx.x < NEXP) cnt[threadIdx.x] = 0; }

__global__ __launch_bounds__(256) void k_gate(
    const float* __restrict__ x, const float* __restrict__ gw,
    int* cnt, int* list, int* slot, float* wt)
{
    int t = blockIdx.x;
    int lane = threadIdx.x & 31, wrp = threadIdx.x >> 5;   // 8 warps, one per expert
    const float* xr = x + (size_t)t * HDIM;
    float s = 0.f;
    for (int d = lane; d < HDIM; d += 32) s += xr[d] * gw[(size_t)d*NEXP + wrp];
#pragma unroll
    for (int o = 16; o > 0; o >>= 1) s += __shfl_xor_sync(0xffffffffu, s, o);
    __shared__ float logits[NEXP];
    if (lane == 0) logits[wrp] = s;
    __syncthreads();
    if (threadIdx.x == 0) {
        int i0 = 0; float v0 = logits[0];
#pragma unroll
        for (int e = 1; e < NEXP; e++) if (logits[e] > v0) { v0 = logits[e]; i0 = e; }
        int i1 = -1; float v1 = -1e30f;
#pragma unroll
        for (int e = 0; e < NEXP; e++) if (e != i0 && logits[e] > v1) { v1 = logits[e]; i1 = e; }
        float e1 = expf(v1 - v0);
        float inv = 1.f / (1.f + e1);
        float w0 = inv, w1 = e1 * inv;
        int r0 = atomicAdd(&cnt[i0], 1);
        list[i0*S_LEN + r0] = t;
        slot[t*2 + 0] = i0*S_LEN + r0;  wt[t*2 + 0] = w0;
        int r1 = atomicAdd(&cnt[i1], 1);
        list[i1*S_LEN + r1] = t;
        slot[t*2 + 1] = i1*S_LEN + r1;  wt[t*2 + 1] = w1;
    }
}

// ---------------- MoE elementwise: u = silu(u) * t --------------------------
__global__ __launch_bounds__(256) void k_silu_mul(
    float* __restrict__ u, const float* __restrict__ tt, const int* __restrict__ cnt)
{
    int e = blockIdx.z, row = blockIdx.y;
    if (row >= cnt[e]) return;
    size_t base = ((size_t)e*S_LEN + row) * IDIM;
    int c = blockIdx.x*256 + threadIdx.x;
    float uu = u[base + c];
    float sv = uu / (1.f + expf(-uu));
    u[base + c] = sv * tt[base + c];
}

// ---------------- MoE combine: h += RES*(w0*y0 + w1*y1) ---------------------
__global__ __launch_bounds__(256) void k_combine(
    float* __restrict__ h, const float* __restrict__ y,
    const int* __restrict__ slot, const float* __restrict__ wt)
{
    int t = blockIdx.x;
    int s0 = slot[t*2], s1 = slot[t*2 + 1];
    float w0 = wt[t*2], w1 = wt[t*2 + 1];
    const float* y0 = y + (size_t)s0 * HDIM;
    const float* y1 = y + (size_t)s1 * HDIM;
    float* hr = h + (size_t)t * HDIM;
    for (int c = threadIdx.x; c < HDIM; c += 256)
        hr[c] += RES_MULT_F * (w0*y0[c] + w1*y1[c]);
}

// ---------------- host orchestration ----------------------------------------
extern "C" void kernel_launch(void* const* d_in, const int* in_sizes, int n_in,
                              void* d_out, int out_size)
{
    const int*   ids   = (const int*)  d_in[0];
    const int*   pos   = (const int*)  d_in[1];
    const float* embed = (const float*)d_in[2];
    const float* ln1   = (const float*)d_in[3];
    const float* Wq    = (const float*)d_in[4];
    const float* Wk    = (const float*)d_in[5];
    const float* Wv    = (const float*)d_in[6];
    const float* Wo    = (const float*)d_in[7];
    const float* ln2   = (const float*)d_in[8];
    const float* gate  = (const float*)d_in[9];
    const float* w1    = (const float*)d_in[10];
    const float* w3    = (const float*)d_in[11];
    const float* w2    = (const float*)d_in[12];
    const float* normw = (const float*)d_in[13];

    float *ph, *px, *pq, *pk, *pv, *pao, *pu, *pt, *py, *pwt;
    int *pcnt, *plist, *pslot;
    cudaGetSymbolAddress((void**)&ph,   g_h);
    cudaGetSymbolAddress((void**)&px,   g_x);
    cudaGetSymbolAddress((void**)&pq,   g_q);
    cudaGetSymbolAddress((void**)&pk,   g_k);
    cudaGetSymbolAddress((void**)&pv,   g_v);
    cudaGetSymbolAddress((void**)&pao,  g_ao);
    cudaGetSymbolAddress((void**)&pu,   g_u);
    cudaGetSymbolAddress((void**)&pt,   g_t);
    cudaGetSymbolAddress((void**)&py,   g_y);
    cudaGetSymbolAddress((void**)&pwt,  g_wt);
    cudaGetSymbolAddress((void**)&pcnt, g_cnt);
    cudaGetSymbolAddress((void**)&plist,g_list);
    cudaGetSymbolAddress((void**)&pslot,g_slot);

    k_embed<<<S_LEN, 256>>>(ids, embed, ph);

    for (int l = 0; l < NLAYER; l++) {
        // --- attention block ---
        k_rmsnorm<<<S_LEN, 256>>>(ph, ln1 + (size_t)l*HDIM, px);

        k_sgemm_qkv<<<dim3(16, S_LEN/BM), 256>>>(
            px,
            Wq + (size_t)l*HDIM*1024, Wk + (size_t)l*HDIM*512, Wv + (size_t)l*HDIM*512,
            pq, pk, pv);

        k_rope<<<S_LEN, 256>>>(pq, pk, pos);

        k_flash<<<dim3(NHEADS, S_LEN/64), 64>>>(pq, pk, pv, pao);

        k_sgemm<<<dim3(HDIM/BN, S_LEN/BM), 256>>>(pao, Wo + (size_t)l*1024*HDIM, ph,
                                                  S_LEN, HDIM, 1024, RES_MULT_F, 1);

        // --- MoE block ---
        k_rmsnorm<<<S_LEN, 256>>>(ph, ln2 + (size_t)l*HDIM, px);
        k_zero_cnt<<<1, 32>>>(pcnt);
        k_gate<<<S_LEN, 256>>>(px, gate + (size_t)l*HDIM*NEXP, pcnt, plist, pslot, pwt);

        k_sgemm_moe<<<dim3(IDIM/BN, S_LEN/BM, NEXP), 256>>>(
            px, 0L,
            w1 + (size_t)l*NEXP*HDIM*IDIM, (long)HDIM*IDIM,
            pu, (long)S_LEN*IDIM,
            plist, pcnt, IDIM, HDIM);

        k_sgemm_moe<<<dim3(IDIM/BN, S_LEN/BM, NEXP), 256>>>(
            px, 0L,
            w3 + (size_t)l*NEXP*HDIM*IDIM, (long)HDIM*IDIM,
            pt, (long)S_LEN*IDIM,
            plist, pcnt, IDIM, HDIM);

        k_silu_mul<<<dim3(IDIM/256, S_LEN, NEXP), 256>>>(pu, pt, pcnt);

        k_sgemm_moe<<<dim3(HDIM/BN, S_LEN/BM, NEXP), 256>>>(
            pu, (long)S_LEN*IDIM,
            w2 + (size_t)l*NEXP*IDIM*HDIM, (long)IDIM*HDIM,
            py, (long)S_LEN*HDIM,
            nullptr, pcnt, HDIM, IDIM);

        k_combine<<<S_LEN, 256>>>(ph, py, pslot, pwt);
    }

    k_rmsnorm<<<S_LEN, 256>>>(ph, normw, (float*)d_out);
}

// round 13
// speedup vs baseline: 1.0044x; 1.0044x over previous
#include <cuda_runtime.h>
#include <math.h>
#include <stdint.h>

#define S_LEN 2048
#define HDIM  1024
#define NHEADS 16
#define NKVH   8
#define DHEAD  64
#define NLAYER 2
#define NEXP   8
#define TOPK   2
#define IDIM   1024
#define EMB_MULT_F 12.0f
#define RES_MULT_F 0.22f
#define ATTN_MULT_F 0.015625f

// ---------------- scratch (static device globals; no runtime allocation) ----
__device__ float g_h [S_LEN*HDIM];
__device__ float g_x [S_LEN*HDIM];
__device__ float g_q [S_LEN*NHEADS*DHEAD];
__device__ float g_k [S_LEN*NKVH*DHEAD];
__device__ float g_v [S_LEN*NKVH*DHEAD];
__device__ float g_ao[S_LEN*NHEADS*DHEAD];
__device__ float g_u [(size_t)NEXP*S_LEN*IDIM];
__device__ float g_t [(size_t)NEXP*S_LEN*IDIM];
__device__ float g_y [(size_t)NEXP*S_LEN*HDIM];
__device__ int   g_cnt [NEXP];
__device__ int   g_list[NEXP*S_LEN];
__device__ int   g_slot[S_LEN*TOPK];
__device__ float g_wt  [S_LEN*TOPK];

// ---------------- tf32 tensor-core GEMM: 128x128 tile, BK=16, 8 warps -------
// 2-stage shared-memory double buffer: one __syncthreads per K-tile.
#define BM 128
#define BN 128
#define BKT 16
#define AS_STRIDE 20    // conflict-free for A-fragment LDS pattern
#define BS_STRIDE 136   // conflict-free for B-fragment LDS pattern

__device__ __forceinline__ uint32_t f2tf(float f) {
    uint32_t u; asm("cvt.rna.tf32.f32 %0, %1;" : "=r"(u) : "f"(f)); return u;
}

__device__ __forceinline__ void mma8(float* d, const uint32_t* a, const uint32_t* b) {
    asm volatile(
        "mma.sync.aligned.m16n8k8.row.col.f32.tf32.tf32.f32 "
        "{%0,%1,%2,%3},{%4,%5,%6,%7},{%8,%9},{%0,%1,%2,%3};"
        : "+f"(d[0]), "+f"(d[1]), "+f"(d[2]), "+f"(d[3])
        : "r"(a[0]), "r"(a[1]), "r"(a[2]), "r"(a[3]), "r"(b[0]), "r"(b[1]));
}

__device__ __forceinline__ void mma_core(
    const float* __restrict__ A, const float* __restrict__ B, float* __restrict__ C,
    int Meff, int N, int K, int col0, const int* __restrict__ gather,
    float alpha, bool accum)
{
    __shared__ __align__(16) uint32_t As[2][BM*AS_STRIDE];
    __shared__ __align__(16) uint32_t Bs[2][BKT*BS_STRIDE];

    int row0 = blockIdx.y * BM;
    if (row0 >= Meff) return;
    int tid  = threadIdx.x;
    int lane = tid & 31, wid = tid >> 5;
    int wm = wid & 3, wn = wid >> 2;      // warp tile: rows wm*32, cols wn*64

    // A loader: thread -> (row = tid>>1, cols (tid&1)*8 .. +7)
    int arow = tid >> 1;
    int acol = (tid & 1) * 8;
    int grow = row0 + arow;
    bool aok = (grow < Meff);
    const float* Arow = A;
    if (aok) { int src = gather ? gather[grow] : grow; Arow = A + (size_t)src * K; }
    // B loader: thread -> (row = tid>>4, cols (tid&15)*8 .. +7)
    int brow = tid >> 4;
    int bcol = (tid & 15) * 8;
    const float* Bp = B + (size_t)brow * N + col0 + bcol;

    float acc[2][8][4];
#pragma unroll
    for (int mt = 0; mt < 2; mt++)
#pragma unroll
        for (int nt = 0; nt < 8; nt++)
#pragma unroll
            for (int i = 0; i < 4; i++) acc[mt][nt][i] = 0.f;

    float ra[8], rb[8];

    auto LOADT = [&](int k0) {
        if (aok) {
            float4 t0 = *(const float4*)(Arow + k0 + acol);
            float4 t1 = *(const float4*)(Arow + k0 + acol + 4);
            ra[0]=t0.x; ra[1]=t0.y; ra[2]=t0.z; ra[3]=t0.w;
            ra[4]=t1.x; ra[5]=t1.y; ra[6]=t1.z; ra[7]=t1.w;
        } else {
#pragma unroll
            for (int i = 0; i < 8; i++) ra[i] = 0.f;
        }
        float4 u0 = *(const float4*)(Bp + (size_t)k0 * N);
        float4 u1 = *(const float4*)(Bp + (size_t)k0 * N + 4);
        rb[0]=u0.x; rb[1]=u0.y; rb[2]=u0.z; rb[3]=u0.w;
        rb[4]=u1.x; rb[5]=u1.y; rb[6]=u1.z; rb[7]=u1.w;
    };
    auto STORET = [&](int st) {
        uint4 pa0 = make_uint4(f2tf(ra[0]), f2tf(ra[1]), f2tf(ra[2]), f2tf(ra[3]));
        uint4 pa1 = make_uint4(f2tf(ra[4]), f2tf(ra[5]), f2tf(ra[6]), f2tf(ra[7]));
        *(uint4*)&As[st][arow*AS_STRIDE + acol]     = pa0;
        *(uint4*)&As[st][arow*AS_STRIDE + acol + 4] = pa1;
        uint4 pb0 = make_uint4(f2tf(rb[0]), f2tf(rb[1]), f2tf(rb[2]), f2tf(rb[3]));
        uint4 pb1 = make_uint4(f2tf(rb[4]), f2tf(rb[5]), f2tf(rb[6]), f2tf(rb[7]));
        *(uint4*)&Bs[st][brow*BS_STRIDE + bcol]     = pb0;
        *(uint4*)&Bs[st][brow*BS_STRIDE + bcol + 4] = pb1;
    };
    auto COMPUTE = [&](int st) {
#pragma unroll
        for (int ks = 0; ks < 2; ks++) {
            const int kk = ks * 8;
            uint32_t af[2][4];
            int r    = wm*32 + (lane >> 2);
            int ccol = kk + (lane & 3);
#pragma unroll
            for (int mt = 0; mt < 2; mt++) {
                int rr = r + mt*16;
                af[mt][0] = As[st][(rr    )*AS_STRIDE + ccol];
                af[mt][1] = As[st][(rr + 8)*AS_STRIDE + ccol];
                af[mt][2] = As[st][(rr    )*AS_STRIDE + ccol + 4];
                af[mt][3] = As[st][(rr + 8)*AS_STRIDE + ccol + 4];
            }
#pragma unroll
            for (int nt = 0; nt < 8; nt++) {
                int cn = wn*64 + nt*8 + (lane >> 2);
                uint32_t bf[2];
                bf[0] = Bs[st][(kk + (lane & 3)    )*BS_STRIDE + cn];
                bf[1] = Bs[st][(kk + (lane & 3) + 4)*BS_STRIDE + cn];
                mma8(acc[0][nt], af[0], bf);
                mma8(acc[1][nt], af[1], bf);
            }
        }
    };

    LOADT(0);
    STORET(0);
    __syncthreads();
    int stage = 0;
    for (int k0 = BKT; k0 < K; k0 += BKT) {
        LOADT(k0);              // prefetch next tile into registers
        COMPUTE(stage);         // compute current smem stage
        STORET(stage ^ 1);      // write next stage (no conflict with compute)
        __syncthreads();
        stage ^= 1;
    }
    COMPUTE(stage);

    // epilogue
#pragma unroll
    for (int mt = 0; mt < 2; mt++) {
        int rbase = row0 + wm*32 + mt*16 + (lane >> 2);
#pragma unroll
        for (int half = 0; half < 2; half++) {
            int r = rbase + half*8;
            if (r >= Meff) continue;
            float* Crow = C + (size_t)r * N;
#pragma unroll
            for (int nt = 0; nt < 8; nt++) {
                int c = col0 + wn*64 + nt*8 + (lane & 3)*2;
                float x = alpha * acc[mt][nt][half*2 + 0];
                float y = alpha * acc[mt][nt][half*2 + 1];
                if (accum) {
                    Crow[c]   += x;
                    Crow[c+1] += y;
                } else {
                    float2 vv = make_float2(x, y);
                    *(float2*)(Crow + c) = vv;
                }
            }
        }
    }
}

__global__ __launch_bounds__(256) void k_sgemm(
    const float* A, const float* B, float* C,
    int M, int N, int K, float alpha, int accum)
{
    mma_core(A, B, C, M, N, K, blockIdx.x*BN, nullptr, alpha, accum != 0);
}

// fused QKV: one launch, blockIdx.x 0..15 spans q(0-7), k(8-11), v(12-15)
__global__ __launch_bounds__(256) void k_sgemm_qkv(
    const float* __restrict__ A,
    const float* __restrict__ Wq, const float* __restrict__ Wk, const float* __restrict__ Wv,
    float* __restrict__ q, float* __restrict__ k, float* __restrict__ v)
{
    int nb = blockIdx.x;
    const float* B; float* C; int N; int cb;
    if (nb < 8)       { B = Wq; C = q; N = 1024; cb = nb; }
    else if (nb < 12) { B = Wk; C = k; N = 512;  cb = nb - 8; }
    else              { B = Wv; C = v; N = 512;  cb = nb - 12; }
    mma_core(A, B, C, S_LEN, N, HDIM, cb*BN, nullptr, 1.f, false);
}

// one launch covers all 8 experts via blockIdx.z; blocks past cnt[e] exit early
__global__ __launch_bounds__(256) void k_sgemm_moe(
    const float* A, long aStride,
    const float* B, long bStride,
    float* C, long cStride,
    const int* gatherBase, const int* cnt, int N, int K)
{
    int e = blockIdx.z;
    mma_core(A + (size_t)e*aStride, B + (size_t)e*bStride, C + (size_t)e*cStride,
             cnt[e], N, K, blockIdx.x*BN,
             gatherBase ? gatherBase + e*S_LEN : nullptr, 1.f, false);
}

// ---------------- embedding ------------------------------------------------
__global__ __launch_bounds__(256) void k_embed(
    const int* __restrict__ ids, const float* __restrict__ emb, float* __restrict__ h)
{
    int t = blockIdx.x;
    int id = ids[t];
    const float* er = emb + (size_t)id * HDIM;
    for (int c = threadIdx.x; c < HDIM; c += 256)
        h[(size_t)t*HDIM + c] = er[c] * EMB_MULT_F;
}

// ---------------- rmsnorm ---------------------------------------------------
__global__ __launch_bounds__(256) void k_rmsnorm(
    const float* __restrict__ in, const float* __restrict__ w, float* __restrict__ out)
{
    int t = blockIdx.x;
    const float* xr = in + (size_t)t * HDIM;
    float s = 0.f;
    for (int c = threadIdx.x; c < HDIM; c += 256) { float vv = xr[c]; s += vv*vv; }
    __shared__ float red[256];
    red[threadIdx.x] = s;
    __syncthreads();
    for (int o = 128; o > 0; o >>= 1) {
        if (threadIdx.x < o) red[threadIdx.x] += red[threadIdx.x + o];
        __syncthreads();
    }
    float scale = rsqrtf(red[0] * (1.f/HDIM) + 1e-6f);
    for (int c = threadIdx.x; c < HDIM; c += 256)
        out[(size_t)t*HDIM + c] = xr[c] * scale * w[c];
}

// ---------------- RoPE (neox halves), fp32, sincos cached in smem -----------
// exponent: inv_freq(j) = 10000^(-2j/64) = exp2f(-j * log2(10000)/32)
__global__ __launch_bounds__(256) void k_rope(
    float* __restrict__ q, float* __restrict__ kk, const int* __restrict__ pos)
{
    int t = blockIdx.x;
    __shared__ float sc[32], ss[32];
    if (threadIdx.x < 32) {
        float p = (float)pos[t];
        float invf = exp2f((float)threadIdx.x * -0.4152410118f);
        float ang = p * invf;
        ss[threadIdx.x] = sinf(ang);
        sc[threadIdx.x] = cosf(ang);
    }
    __syncthreads();
    // 768 items: (head 0..23) x (pair j 0..31); heads 0-15 -> q, 16-23 -> k
#pragma unroll
    for (int it = threadIdx.x; it < 768; it += 256) {
        int hh = it >> 5, j = it & 31;
        float* base = (hh < 16)
            ? q  + (size_t)t*(NHEADS*DHEAD) + hh*DHEAD
            : kk + (size_t)t*(NKVH*DHEAD)   + (hh - 16)*DHEAD;
        float x1 = base[j], x2 = base[j + 32];
        base[j]      = x1*sc[j] - x2*ss[j];
        base[j + 32] = x2*sc[j] + x1*ss[j];
    }
}

// ---------------- flash attention (fp32, causal, GQA rep=2) -----------------
// float4-vectorized: 4 parallel dot partials break the serial FMA chain.
__global__ __launch_bounds__(64) void k_flash(
    const float* __restrict__ q, const float* __restrict__ k,
    const float* __restrict__ v, float* __restrict__ out)
{
    int head = blockIdx.x;        // 0..15
    int qt   = blockIdx.y;        // 0..31
    int tid  = threadIdx.x;       // 64: one q row per thread
    int m = qt*64 + tid;
    int kvh = head >> 1;

    __shared__ __align__(16) float4 Ks[64][16];
    __shared__ __align__(16) float4 Vs[64][16];

    float4 qv[16], av[16];
    const float4* qp = (const float4*)(q + (size_t)m*(NHEADS*DHEAD) + head*DHEAD);
#pragma unroll
    for (int i = 0; i < 16; i++) {
        float4 tq = qp[i];
        tq.x *= ATTN_MULT_F; tq.y *= ATTN_MULT_F; tq.z *= ATTN_MULT_F; tq.w *= ATTN_MULT_F;
        qv[i] = tq;
        av[i] = make_float4(0.f, 0.f, 0.f, 0.f);
    }

    float mi = -1e30f, li = 0.f;

    for (int jt = 0; jt <= qt; jt++) {
        const float4* kp = (const float4*)(k + (size_t)(jt*64)*(NKVH*DHEAD) + kvh*DHEAD);
        const float4* vp = (const float4*)(v + (size_t)(jt*64)*(NKVH*DHEAD) + kvh*DHEAD);
#pragma unroll
        for (int i = 0; i < 16; i++) {
            int idx = i*64 + tid;
            int r = idx >> 4, c = idx & 15;
            size_t off = (size_t)r * (NKVH*DHEAD/4) + c;
            Ks[r][c] = kp[off];
            Vs[r][c] = vp[off];
        }
        __syncthreads();
        int jmax = (jt == qt) ? (tid + 1) : 64;   // causal within diagonal tile
        for (int j = 0; j < jmax; j++) {
            float4 s4 = make_float4(0.f, 0.f, 0.f, 0.f);
#pragma unroll
            for (int i = 0; i < 16; i++) {
                float4 kk4 = Ks[j][i];
                s4.x += qv[i].x * kk4.x;
                s4.y += qv[i].y * kk4.y;
                s4.z += qv[i].z * kk4.z;
                s4.w += qv[i].w * kk4.w;
            }
            float s = (s4.x + s4.y) + (s4.z + s4.w);
            if (s > mi) {
                float corr = __expf(mi - s);
                li = li*corr + 1.f;
#pragma unroll
                for (int i = 0; i < 16; i++) {
                    float4 vv = Vs[j][i];
                    av[i].x = av[i].x*corr + vv.x;
                    av[i].y = av[i].y*corr + vv.y;
                    av[i].z = av[i].z*corr + vv.z;
                    av[i].w = av[i].w*corr + vv.w;
                }
                mi = s;
            } else {
                float pp = __expf(s - mi);
                li += pp;
#pragma unroll
                for (int i = 0; i < 16; i++) {
                    float4 vv = Vs[j][i];
                    av[i].x += pp*vv.x;
                    av[i].y += pp*vv.y;
                    av[i].z += pp*vv.z;
                    av[i].w += pp*vv.w;
                }
            }
        }
        __syncthreads();
    }
    float inv = 1.f / li;
    float4* op = (float4*)(out + (size_t)m*(NHEADS*DHEAD) + head*DHEAD);
#pragma unroll
    for (int i = 0; i < 16; i++) {
        float4 r = av[i];
        r.x *= inv; r.y *= inv; r.z *= inv; r.w *= inv;
        op[i] = r;
    }
}

// ---------------- gating: logits, top-2, softmax, expert lists --------------
__global__ void k_zero_cnt(int* cnt) { if (threadIdx.x < NEXP) cnt[threadIdx.x] = 0; }

__global__ __launch_bounds__(256) void k_gate(
    const float* __restrict__ x, const float* __restrict__ gw,
    int* cnt, int* list, int* slot, float* wt)
{
    int t = blockIdx.x;
    int lane = threadIdx.x & 31, wrp = threadIdx.x >> 5;   // 8 warps, one per expert
    const float* xr = x + (size_t)t * HDIM;
    float s = 0.f;
    for (int d = lane; d < HDIM; d += 32) s += xr[d] * gw[(size_t)d*NEXP + wrp];
#pragma unroll
    for (int o = 16; o > 0; o >>= 1) s += __shfl_xor_sync(0xffffffffu, s, o);
    __shared__ float logits[NEXP];
    if (lane == 0) logits[wrp] = s;
    __syncthreads();
    if (threadIdx.x == 0) {
        int i0 = 0; float v0 = logits[0];
#pragma unroll
        for (int e = 1; e < NEXP; e++) if (logits[e] > v0) { v0 = logits[e]; i0 = e; }
        int i1 = -1; float v1 = -1e30f;
#pragma unroll
        for (int e = 0; e < NEXP; e++) if (e != i0 && logits[e] > v1) { v1 = logits[e]; i1 = e; }
        float e1 = expf(v1 - v0);
        float inv = 1.f / (1.f + e1);
        float w0 = inv, w1 = e1 * inv;
        int r0 = atomicAdd(&cnt[i0], 1);
        list[i0*S_LEN + r0] = t;
        slot[t*2 + 0] = i0*S_LEN + r0;  wt[t*2 + 0] = w0;
        int r1 = atomicAdd(&cnt[i1], 1);
        list[i1*S_LEN + r1] = t;
        slot[t*2 + 1] = i1*S_LEN + r1;  wt[t*2 + 1] = w1;
    }
}

// ---------------- MoE elementwise: u = silu(u) * t --------------------------
__global__ __launch_bounds__(256) void k_silu_mul(
    float* __restrict__ u, const float* __restrict__ tt, const int* __restrict__ cnt)
{
    int e = blockIdx.z, row = blockIdx.y;
    if (row >= cnt[e]) return;
    size_t base = ((size_t)e*S_LEN + row) * IDIM;
    int c = blockIdx.x*256 + threadIdx.x;
    float uu = u[base + c];
    float sv = uu / (1.f + expf(-uu));
    u[base + c] = sv * tt[base + c];
}

// ---------------- MoE combine: h += RES*(w0*y0 + w1*y1) ---------------------
__global__ __launch_bounds__(256) void k_combine(
    float* __restrict__ h, const float* __restrict__ y,
    const int* __restrict__ slot, const float* __restrict__ wt)
{
    int t = blockIdx.x;
    int s0 = slot[t*2], s1 = slot[t*2 + 1];
    float w0 = wt[t*2], w1 = wt[t*2 + 1];
    const float* y0 = y + (size_t)s0 * HDIM;
    const float* y1 = y + (size_t)s1 * HDIM;
    float* hr = h + (size_t)t * HDIM;
    for (int c = threadIdx.x; c < HDIM; c += 256)
        hr[c] += RES_MULT_F * (w0*y0[c] + w1*y1[c]);
}

// ---------------- host orchestration ----------------------------------------
extern "C" void kernel_launch(void* const* d_in, const int* in_sizes, int n_in,
                              void* d_out, int out_size)
{
    const int*   ids   = (const int*)  d_in[0];
    const int*   pos   = (const int*)  d_in[1];
    const float* embed = (const float*)d_in[2];
    const float* ln1   = (const float*)d_in[3];
    const float* Wq    = (const float*)d_in[4];
    const float* Wk    = (const float*)d_in[5];
    const float* Wv    = (const float*)d_in[6];
    const float* Wo    = (const float*)d_in[7];
    const float* ln2   = (const float*)d_in[8];
    const float* gate  = (const float*)d_in[9];
    const float* w1    = (const float*)d_in[10];
    const float* w3    = (const float*)d_in[11];
    const float* w2    = (const float*)d_in[12];
    const float* normw = (const float*)d_in[13];

    float *ph, *px, *pq, *pk, *pv, *pao, *pu, *pt, *py, *pwt;
    int *pcnt, *plist, *pslot;
    cudaGetSymbolAddress((void**)&ph,   g_h);
    cudaGetSymbolAddress((void**)&px,   g_x);
    cudaGetSymbolAddress((void**)&pq,   g_q);
    cudaGetSymbolAddress((void**)&pk,   g_k);
    cudaGetSymbolAddress((void**)&pv,   g_v);
    cudaGetSymbolAddress((void**)&pao,  g_ao);
    cudaGetSymbolAddress((void**)&pu,   g_u);
    cudaGetSymbolAddress((void**)&pt,   g_t);
    cudaGetSymbolAddress((void**)&py,   g_y);
    cudaGetSymbolAddress((void**)&pwt,  g_wt);
    cudaGetSymbolAddress((void**)&pcnt, g_cnt);
    cudaGetSymbolAddress((void**)&plist,g_list);
    cudaGetSymbolAddress((void**)&pslot,g_slot);

    k_embed<<<S_LEN, 256>>>(ids, embed, ph);

    for (int l = 0; l < NLAYER; l++) {
        // --- attention block ---
        k_rmsnorm<<<S_LEN, 256>>>(ph, ln1 + (size_t)l*HDIM, px);

        k_sgemm_qkv<<<dim3(16, S_LEN/BM), 256>>>(
            px,
            Wq + (size_t)l*HDIM*1024, Wk + (size_t)l*HDIM*512, Wv + (size_t)l*HDIM*512,
            pq, pk, pv);

        k_rope<<<S_LEN, 256>>>(pq, pk, pos);

        k_flash<<<dim3(NHEADS, S_LEN/64), 64>>>(pq, pk, pv, pao);

        k_sgemm<<<dim3(HDIM/BN, S_LEN/BM), 256>>>(pao, Wo + (size_t)l*1024*HDIM, ph,
                                                  S_LEN, HDIM, 1024, RES_MULT_F, 1);

        // --- MoE block ---
        k_rmsnorm<<<S_LEN, 256>>>(ph, ln2 + (size_t)l*HDIM, px);
        k_zero_cnt<<<1, 32>>>(pcnt);
        k_gate<<<S_LEN, 256>>>(px, gate + (size_t)l*HDIM*NEXP, pcnt, plist, pslot, pwt);

        k_sgemm_moe<<<dim3(IDIM/BN, S_LEN/BM, NEXP), 256>>>(
            px, 0L,
            w1 + (size_t)l*NEXP*HDIM*IDIM, (long)HDIM*IDIM,
            pu, (long)S_LEN*IDIM,
            plist, pcnt, IDIM, HDIM);

        k_sgemm_moe<<<dim3(IDIM/BN, S_LEN/BM, NEXP), 256>>>(
            px, 0L,
            w3 + (size_t)l*NEXP*HDIM*IDIM, (long)HDIM*IDIM,
            pt, (long)S_LEN*IDIM,
            plist, pcnt, IDIM, HDIM);

        k_silu_mul<<<dim3(IDIM/256, S_LEN, NEXP), 256>>>(pu, pt, pcnt);

        k_sgemm_moe<<<dim3(HDIM/BN, S_LEN/BM, NEXP), 256>>>(
            pu, (long)S_LEN*IDIM,
            w2 + (size_t)l*NEXP*IDIM*HDIM, (long)IDIM*HDIM,
            py, (long)S_LEN*HDIM,
            nullptr, pcnt, HDIM, IDIM);

        k_combine<<<S_LEN, 256>>>(ph, py, pslot, pwt);
    }

    k_rmsnorm<<<S_LEN, 256>>>(ph, normw, (float*)d_out);
}